// round 13
// baseline (speedup 1.0000x reference)
#include <cuda_runtime.h>
#include <cuda_fp16.h>
#include <cstdint>
#include <cstddef>

// ---------------------------------------------------------------------------
// TSABlock, plain-fp16 mma.sync HMMA (tcgen05 blocked: harness PTX targets
// compute_103 without the 'a' feature set).
// GEMMs: A fp16, W fp16, fp32 accumulate (calibrated rel_err ~5.2e-4).
// R12: warp tile 64x64 (was 64x32), block 128x256, 1 CTA/SM, 144KB smem.
// LDSM:MMA ratio 0.25 (was 0.375) -> tensor pipe becomes sole binding pipe.
// Attention fully row-local (HEADS==CLIP==8 torch-.view quirk).
// ---------------------------------------------------------------------------

#define BSZ     8192
#define IN_CH   1024
#define OUT_CH  512
#define T_DIM   512
#define ROWS    65536

__device__ __half g_t16 [(size_t)BSZ  * T_DIM];
__device__ __half g_x16 [(size_t)ROWS * IN_CH];
__device__ __half g_wd2 [(size_t)OUT_CH * IN_CH];
__device__ __half g_wt2 [(size_t)OUT_CH * T_DIM];
__device__ __half g_wq2 [(size_t)3 * OUT_CH * OUT_CH];
__device__ __half g_wo2 [(size_t)OUT_CH * OUT_CH];
__device__ float  g_temb[(size_t)BSZ * OUT_CH];
__device__ __half g_h2  [(size_t)ROWS * OUT_CH];
__device__ __half g_qkv [(size_t)ROWS * 3 * OUT_CH];
__device__ __half g_at2 [(size_t)ROWS * OUT_CH];

// ---------------------------- helpers --------------------------------------
__device__ __forceinline__ uint32_t smem_u32(const void* p) {
    uint32_t a;
    asm("{ .reg .u64 t; cvta.to.shared.u64 t, %1; cvt.u32.u64 %0, t; }"
        : "=r"(a) : "l"(p));
    return a;
}
__device__ __forceinline__ void ldsm4(uint32_t* r, uint32_t addr) {
    asm volatile("ldmatrix.sync.aligned.m8n8.x4.shared.b16 {%0,%1,%2,%3}, [%4];"
                 : "=r"(r[0]), "=r"(r[1]), "=r"(r[2]), "=r"(r[3]) : "r"(addr));
}
__device__ __forceinline__ void mma16816(float* d, const uint32_t* a,
                                         uint32_t b0, uint32_t b1) {
    asm volatile("mma.sync.aligned.m16n8k16.row.col.f32.f16.f16.f32 "
                 "{%0,%1,%2,%3}, {%4,%5,%6,%7}, {%8,%9}, {%0,%1,%2,%3};"
                 : "+f"(d[0]), "+f"(d[1]), "+f"(d[2]), "+f"(d[3])
                 : "r"(a[0]), "r"(a[1]), "r"(a[2]), "r"(a[3]), "r"(b0), "r"(b1));
}
#define CP_ASYNC(dst, src) \
    asm volatile("cp.async.cg.shared.global [%0], [%1], 16;" :: "r"(dst), "l"(src))
#define CP_COMMIT() asm volatile("cp.async.commit_group;" ::: "memory")
#define CP_WAIT(n)  asm volatile("cp.async.wait_group %0;" :: "n"(n) : "memory")

__device__ __forceinline__ uint32_t pk2h(__half a, __half b) {
    return (uint32_t)__half_as_ushort(a) | ((uint32_t)__half_as_ushort(b) << 16);
}

// ---------------------------------------------------------------------------
// conv_all: single elementwise fp32->fp16 pass over all 6 tensors.
// ---------------------------------------------------------------------------
#define CONV_TOTAL4 18284544L

__global__ void conv_all(const float4* __restrict__ wd, const float4* __restrict__ wt,
                         const float4* __restrict__ wq, const float4* __restrict__ wo,
                         const float4* __restrict__ t,  const float4* __restrict__ x,
                         __half* __restrict__ od, __half* __restrict__ ot,
                         __half* __restrict__ oq, __half* __restrict__ oo,
                         __half* __restrict__ o_t, __half* __restrict__ o_x)
{
    long idx = (long)blockIdx.x * blockDim.x + threadIdx.x;
    if (idx >= CONV_TOTAL4) return;
    const float4* in; __half* out; long lidx;
    if (idx >= 1507328L)      { in = x;  out = o_x; lidx = idx - 1507328L; }
    else if (idx >= 458752L)  { in = t;  out = o_t; lidx = idx - 458752L; }
    else if (idx >= 393216L)  { in = wo; out = oo;  lidx = idx - 393216L; }
    else if (idx >= 196608L)  { in = wq; out = oq;  lidx = idx - 196608L; }
    else if (idx >= 131072L)  { in = wt; out = ot;  lidx = idx - 131072L; }
    else                      { in = wd; out = od;  lidx = idx; }
    float4 v = in[lidx];
    *(uint2*)(out + lidx * 4) =
        make_uint2(pk2h(__float2half_rn(v.x), __float2half_rn(v.y)),
                   pk2h(__float2half_rn(v.z), __float2half_rn(v.w)));
}

// ---------------------------------------------------------------------------
// GEMM: C[M,N] = A[M,K] @ W[N,K]^T + bias (+extra for MODE 1)
// Block 128x256, BK=64, 3-stage cp.async, 8 warps (2m x 4n), warp 64x64.
// MODE 0: fp32 out, row stride N.
// MODE 1: fp16 out, row stride 512, adds extra[m>>3, col] (temb).
// MODE 2: fp16 out, row stride N.
// ---------------------------------------------------------------------------
#define STAGES      3
#define STAGE_BYTES 49152    // A 16KB + B 32KB

template <int MODE>
__global__ __launch_bounds__(256)
void gemm_mma(const __half* __restrict__ A, const __half* __restrict__ B,
              const float* __restrict__ bias, const float* __restrict__ extra,
              void* __restrict__ Cout, int N, int K)
{
    extern __shared__ char sm[];
    const uint32_t smemBase = smem_u32(sm);
    const int tid    = threadIdx.x;
    const int lane   = tid & 31;
    const int wid    = tid >> 5;
    const int warp_m = wid >> 2;       // 0..1  -> 64 rows each
    const int warp_n = wid & 3;        // 0..3  -> 64 cols each
    const int mB     = blockIdx.y * 128;
    const int nB     = blockIdx.x * 256;

    // cp.async: 3072 16B chunks/stage (A 1024 + B 2048), 12 per thread.
    // row&7 is invariant under +32-row steps, so one swizzle per thread.
    const int rowL = tid >> 3;         // 0..31
    const int cL   = tid & 7;
    const uint32_t swz   = (uint32_t)((cL ^ (rowL & 7)) << 4);
    const uint32_t dstA0 = rowL * 128 + swz;
    const uint32_t dstB0 = 16384 + rowL * 128 + swz;
    const __half* gA = A + (size_t)(mB + rowL) * K + cL * 8;
    const __half* gB = B + (size_t)(nB + rowL) * K + cL * 8;
    const size_t stepA = (size_t)32 * K;   // +32 rows

    // ldmatrix bases (stage 0, k-chunk 0)
    const int la = lane & 15, ha = lane >> 4;
    uint32_t baseA[4];
#pragma unroll
    for (int mi = 0; mi < 4; mi++) {
        int row = warp_m * 64 + mi * 16 + la;
        baseA[mi] = smemBase + row * 128 + ((ha ^ (row & 7)) << 4);
    }
    const int lb = (lane & 7) + ((lane >> 4) << 3);
    const int hb = (lane >> 3) & 1;
    uint32_t baseB[4];
#pragma unroll
    for (int n2 = 0; n2 < 4; n2++) {
        int row = warp_n * 64 + n2 * 16 + lb;
        baseB[n2] = smemBase + 16384 + row * 128 + ((hb ^ (row & 7)) << 4);
    }

    float acc[4][8][4];
#pragma unroll
    for (int mi = 0; mi < 4; mi++)
#pragma unroll
        for (int ni = 0; ni < 8; ni++)
#pragma unroll
            for (int e = 0; e < 4; e++) acc[mi][ni][e] = 0.f;

    const int nIter = K >> 6;

    // prologue: 2 stages
#pragma unroll
    for (int s = 0; s < STAGES - 1; s++) {
        const uint32_t sb = smemBase + s * STAGE_BYTES;
        const int ko = s * 64;
#pragma unroll
        for (int j = 0; j < 4; j++)
            CP_ASYNC(sb + dstA0 + j * 4096, gA + j * stepA + ko);
#pragma unroll
        for (int j = 0; j < 8; j++)
            CP_ASYNC(sb + dstB0 + j * 4096, gB + j * stepA + ko);
        CP_COMMIT();
    }

    int stage = 0;
    for (int it = 0; it < nIter; it++) {
        CP_WAIT(1);
        __syncthreads();

        if (it + STAGES - 1 < nIter) {
            const int pstage = (stage + STAGES - 1 >= STAGES) ? stage - 1 : stage + 2;
            const uint32_t sb = smemBase + pstage * STAGE_BYTES;
            const int ko = (it + STAGES - 1) * 64;
#pragma unroll
            for (int j = 0; j < 4; j++)
                CP_ASYNC(sb + dstA0 + j * 4096, gA + j * stepA + ko);
#pragma unroll
            for (int j = 0; j < 8; j++)
                CP_ASYNC(sb + dstB0 + j * 4096, gB + j * stepA + ko);
        }
        CP_COMMIT();

        const uint32_t stOff = (uint32_t)stage * STAGE_BYTES;
#pragma unroll
        for (int kk = 0; kk < 4; kk++) {
            uint32_t a[4][4], b[4][4];
#pragma unroll
            for (int mi = 0; mi < 4; mi++)
                ldsm4(a[mi], (baseA[mi] + stOff) ^ (kk << 5));
#pragma unroll
            for (int n2 = 0; n2 < 4; n2++)
                ldsm4(b[n2], (baseB[n2] + stOff) ^ (kk << 5));
#pragma unroll
            for (int mi = 0; mi < 4; mi++)
#pragma unroll
                for (int ni = 0; ni < 8; ni++)
                    mma16816(acc[mi][ni], a[mi],
                             b[ni >> 1][(ni & 1) * 2], b[ni >> 1][(ni & 1) * 2 + 1]);
        }
        stage = (stage + 1 == STAGES) ? 0 : stage + 1;
    }

    // ---------------- epilogue ----------------
    const int mWarp = mB + warp_m * 64;
    const int nWarp = nB + warp_n * 64;
    float bv[8][2];
#pragma unroll
    for (int ni = 0; ni < 8; ni++) {
        const int col = nWarp + ni * 8 + (lane & 3) * 2;
        bv[ni][0] = __ldg(bias + col);
        bv[ni][1] = __ldg(bias + col + 1);
    }
#pragma unroll
    for (int mi = 0; mi < 4; mi++) {
#pragma unroll
        for (int ni = 0; ni < 8; ni++) {
            const int row0 = mWarp + mi * 16 + (lane >> 2);
            const int col  = nWarp + ni * 8 + (lane & 3) * 2;
            float v0 = acc[mi][ni][0] + bv[ni][0], v1 = acc[mi][ni][1] + bv[ni][1];
            float v2 = acc[mi][ni][2] + bv[ni][0], v3 = acc[mi][ni][3] + bv[ni][1];
            if (MODE == 1) {
                const float* e0 = extra + (size_t)(row0 >> 3) * OUT_CH + col;
                const float* e1 = extra + (size_t)((row0 + 8) >> 3) * OUT_CH + col;
                v0 += __ldg(e0); v1 += __ldg(e0 + 1);
                v2 += __ldg(e1); v3 += __ldg(e1 + 1);
            }
            if (MODE == 0) {
                float* c0 = (float*)Cout + (size_t)row0 * N + col;
                float* c1 = (float*)Cout + (size_t)(row0 + 8) * N + col;
                *(float2*)c0 = make_float2(v0, v1);
                *(float2*)c1 = make_float2(v2, v3);
            } else {
                const int stride = (MODE == 1) ? OUT_CH : N;
                __half* o0 = (__half*)Cout + (size_t)row0 * stride + col;
                __half* o1 = (__half*)Cout + (size_t)(row0 + 8) * stride + col;
                *(uint32_t*)o0 = pk2h(__float2half_rn(v0), __float2half_rn(v1));
                *(uint32_t*)o1 = pk2h(__float2half_rn(v2), __float2half_rn(v3));
            }
        }
    }
}

// ---------------------------------------------------------------------------
// Per-row attention: raw half2 smem, shuffle softmax, one barrier.
// Block = 256 threads = 4 rows x 64 (qh,kh) threads.
// ---------------------------------------------------------------------------
__global__ __launch_bounds__(256)
void attn_kernel(const __half* __restrict__ qkv, __half* __restrict__ out2)
{
    __shared__ __align__(16) __half s[4][1536];   // 12 KB

    const int tid = threadIdx.x;
    const size_t rowBase = (size_t)blockIdx.x * 4;

    // cooperative raw copy: 4 rows x 1536 halfs = 768 uint4
    const uint4* src = (const uint4*)(qkv + rowBase * 1536);
    uint4* dst = (uint4*)&s[0][0];
    dst[tid]       = src[tid];
    dst[256 + tid] = src[256 + tid];
    dst[512 + tid] = src[512 + tid];
    __syncthreads();

    const int r  = tid >> 6;
    const int j  = tid & 63;
    const int qh = j >> 3;
    const int kh = j & 7;

    const __half* q = &s[r][0];
    const __half* k = &s[r][512];
    const __half* v = &s[r][1024];

    float sc = 0.f;
#pragma unroll
    for (int c = 0; c < 8; c++) {
        const int cc = (kh + c) & 7;
        uint4 qu = *(const uint4*)(q + qh * 64 + cc * 8);
        uint4 ku = *(const uint4*)(k + kh * 64 + cc * 8);
        const __half2* qp = (const __half2*)&qu;
        const __half2* kp = (const __half2*)&ku;
#pragma unroll
        for (int e = 0; e < 4; e++) {
            float2 a = __half22float2(qp[e]);
            float2 b = __half22float2(kp[e]);
            sc += a.x * b.x + a.y * b.y;
        }
    }
    sc *= 0.125f;

    float mx = sc;
#pragma unroll
    for (int d = 1; d < 8; d <<= 1)
        mx = fmaxf(mx, __shfl_xor_sync(0xffffffffu, mx, d, 8));
    float e = __expf(sc - mx);
    float sum = e;
#pragma unroll
    for (int d = 1; d < 8; d <<= 1)
        sum += __shfl_xor_sync(0xffffffffu, sum, d, 8);
    const float wOwn = e / sum;

    const int lane = tid & 31;
    const int gBase = lane & 24;
    float o[8];
#pragma unroll
    for (int i = 0; i < 8; i++) o[i] = 0.f;
#pragma unroll
    for (int kk = 0; kk < 8; kk++) {
        const int kh2 = (kk + kh) & 7;
        const float wv = __shfl_sync(0xffffffffu, wOwn, gBase + kh2);
        uint4 vu = *(const uint4*)(v + kh2 * 64 + kh * 8);
        const __half2* vp = (const __half2*)&vu;
#pragma unroll
        for (int ee = 0; ee < 4; ee++) {
            float2 b = __half22float2(vp[ee]);
            o[2 * ee]     += wv * b.x;
            o[2 * ee + 1] += wv * b.y;
        }
    }

    uint4 hv = make_uint4(
        pk2h(__float2half_rn(o[0]), __float2half_rn(o[1])),
        pk2h(__float2half_rn(o[2]), __float2half_rn(o[3])),
        pk2h(__float2half_rn(o[4]), __float2half_rn(o[5])),
        pk2h(__float2half_rn(o[6]), __float2half_rn(o[7])));
    __half* base = out2 + (rowBase + r) * 512 + qh * 64 + kh * 8;
    *(uint4*)base = hv;
}

// ---------------------------------------------------------------------------
extern "C" void kernel_launch(void* const* d_in, const int* in_sizes, int n_in,
                              void* d_out, int out_size)
{
    const float* x      = (const float*)d_in[0];
    const float* t      = (const float*)d_in[1];
    const float* W_down = (const float*)d_in[2];
    const float* b_down = (const float*)d_in[3];
    const float* W_t    = (const float*)d_in[4];
    const float* b_t    = (const float*)d_in[5];
    const float* W_qkv  = (const float*)d_in[6];
    const float* b_qkv  = (const float*)d_in[7];
    const float* W_out  = (const float*)d_in[8];
    const float* b_out  = (const float*)d_in[9];
    float* out = (float*)d_out;

    void* p;
    __half *t16, *x16, *wd2, *wt2, *wq2, *wo2, *h2, *qkv, *at2;
    float *temb;
    cudaGetSymbolAddress(&p, g_t16);  t16 = (__half*)p;
    cudaGetSymbolAddress(&p, g_x16);  x16 = (__half*)p;
    cudaGetSymbolAddress(&p, g_wd2);  wd2 = (__half*)p;
    cudaGetSymbolAddress(&p, g_wt2);  wt2 = (__half*)p;
    cudaGetSymbolAddress(&p, g_wq2);  wq2 = (__half*)p;
    cudaGetSymbolAddress(&p, g_wo2);  wo2 = (__half*)p;
    cudaGetSymbolAddress(&p, g_temb); temb = (float*)p;
    cudaGetSymbolAddress(&p, g_h2);   h2  = (__half*)p;
    cudaGetSymbolAddress(&p, g_qkv);  qkv = (__half*)p;
    cudaGetSymbolAddress(&p, g_at2);  at2 = (__half*)p;

    const int dynSmem = STAGES * STAGE_BYTES;   // 144 KB
    cudaFuncSetAttribute(gemm_mma<0>, cudaFuncAttributeMaxDynamicSharedMemorySize, dynSmem);
    cudaFuncSetAttribute(gemm_mma<1>, cudaFuncAttributeMaxDynamicSharedMemorySize, dynSmem);
    cudaFuncSetAttribute(gemm_mma<2>, cudaFuncAttributeMaxDynamicSharedMemorySize, dynSmem);

    // 0: all conversions in one wave
    conv_all<<<(int)((CONV_TOTAL4 + 255) / 256), 256>>>(
        (const float4*)W_down, (const float4*)W_t,
        (const float4*)W_qkv, (const float4*)W_out,
        (const float4*)t, (const float4*)x,
        wd2, wt2, wq2, wo2, t16, x16);

    // 1: temb = t @ W_t^T + b_t                       [8192, 512] fp32
    gemm_mma<0><<<dim3(2, 64), 256, dynSmem>>>(t16, wt2, b_t, nullptr, temb,
                                               OUT_CH, T_DIM);
    // 2: x2 = x @ W_down^T + b_down + temb -> fp16    [65536, 512]
    gemm_mma<1><<<dim3(2, 512), 256, dynSmem>>>(x16, wd2, b_down, temb, h2,
                                                OUT_CH, IN_CH);
    // 3: qkv = x2 @ W_qkv^T + b_qkv -> fp16           [65536, 1536]  (ncu slot)
    gemm_mma<2><<<dim3(6, 512), 256, dynSmem>>>(h2, wq2, b_qkv, nullptr, qkv,
                                                3 * OUT_CH, OUT_CH);
    // 4: attention -> fp16                            [65536, 512]
    attn_kernel<<<ROWS / 4, 256>>>(qkv, at2);
    // 5: out = attn @ W_out^T + b_out                 [65536, 512] fp32
    gemm_mma<0><<<dim3(2, 512), 256, dynSmem>>>(at2, wo2, b_out, nullptr, out,
                                                OUT_CH, OUT_CH);
}

// round 14
// speedup vs baseline: 1.0727x; 1.0727x over previous
#include <cuda_runtime.h>
#include <cuda_fp16.h>
#include <cstdint>
#include <cstddef>

// ---------------------------------------------------------------------------
// TSABlock, plain-fp16 mma.sync HMMA (tcgen05 blocked: harness PTX targets
// compute_103 without the 'a' feature set).
// GEMMs: A fp16, W fp16, fp32 accumulate (calibrated rel_err ~5.2e-4).
// R13: revert to R11 GEMM (128x128, warp 64x32, 2 CTA/SM — R12's fat tile
// lost to exposed latency at occ 1). New: GEMM2 ingests x as fp32 directly
// (LDG+cvt+STS A-path), deleting the 402MB x-conversion pass.
// Attention fully row-local (HEADS==CLIP==8 torch-.view quirk).
// ---------------------------------------------------------------------------

#define BSZ     8192
#define IN_CH   1024
#define OUT_CH  512
#define T_DIM   512
#define ROWS    65536

__device__ __half g_t16 [(size_t)BSZ  * T_DIM];
__device__ __half g_wd2 [(size_t)OUT_CH * IN_CH];
__device__ __half g_wt2 [(size_t)OUT_CH * T_DIM];
__device__ __half g_wq2 [(size_t)3 * OUT_CH * OUT_CH];
__device__ __half g_wo2 [(size_t)OUT_CH * OUT_CH];
__device__ float  g_temb[(size_t)BSZ * OUT_CH];
__device__ __half g_h2  [(size_t)ROWS * OUT_CH];
__device__ __half g_qkv [(size_t)ROWS * 3 * OUT_CH];
__device__ __half g_at2 [(size_t)ROWS * OUT_CH];

// ---------------------------- helpers --------------------------------------
__device__ __forceinline__ uint32_t smem_u32(const void* p) {
    uint32_t a;
    asm("{ .reg .u64 t; cvta.to.shared.u64 t, %1; cvt.u32.u64 %0, t; }"
        : "=r"(a) : "l"(p));
    return a;
}
__device__ __forceinline__ void ldsm4(uint32_t* r, uint32_t addr) {
    asm volatile("ldmatrix.sync.aligned.m8n8.x4.shared.b16 {%0,%1,%2,%3}, [%4];"
                 : "=r"(r[0]), "=r"(r[1]), "=r"(r[2]), "=r"(r[3]) : "r"(addr));
}
__device__ __forceinline__ void mma16816(float* d, const uint32_t* a,
                                         uint32_t b0, uint32_t b1) {
    asm volatile("mma.sync.aligned.m16n8k16.row.col.f32.f16.f16.f32 "
                 "{%0,%1,%2,%3}, {%4,%5,%6,%7}, {%8,%9}, {%0,%1,%2,%3};"
                 : "+f"(d[0]), "+f"(d[1]), "+f"(d[2]), "+f"(d[3])
                 : "r"(a[0]), "r"(a[1]), "r"(a[2]), "r"(a[3]), "r"(b0), "r"(b1));
}
#define CP_ASYNC(dst, src) \
    asm volatile("cp.async.cg.shared.global [%0], [%1], 16;" :: "r"(dst), "l"(src))
#define CP_COMMIT() asm volatile("cp.async.commit_group;" ::: "memory")
#define CP_WAIT(n)  asm volatile("cp.async.wait_group %0;" :: "n"(n) : "memory")

__device__ __forceinline__ uint32_t pk2h(__half a, __half b) {
    return (uint32_t)__half_as_ushort(a) | ((uint32_t)__half_as_ushort(b) << 16);
}
__device__ __forceinline__ uint4 cvt8f(const float* p) {
    float4 u = *(const float4*)p;
    float4 v = *(const float4*)(p + 4);
    uint4 r;
    r.x = pk2h(__float2half_rn(u.x), __float2half_rn(u.y));
    r.y = pk2h(__float2half_rn(u.z), __float2half_rn(u.w));
    r.z = pk2h(__float2half_rn(v.x), __float2half_rn(v.y));
    r.w = pk2h(__float2half_rn(v.z), __float2half_rn(v.w));
    return r;
}

// ---------------------------------------------------------------------------
// conv_all: fp32->fp16 for the 4 weight tensors + t (x handled in-GEMM).
// float4 region offsets:
//   wd [0,131072) wt [131072,196608) wq [196608,393216) wo [393216,458752)
//   t  [458752, 1507328)
// ---------------------------------------------------------------------------
#define CONV_TOTAL4 1507328L

__global__ void conv_all(const float4* __restrict__ wd, const float4* __restrict__ wt,
                         const float4* __restrict__ wq, const float4* __restrict__ wo,
                         const float4* __restrict__ t,
                         __half* __restrict__ od, __half* __restrict__ ot,
                         __half* __restrict__ oq, __half* __restrict__ oo,
                         __half* __restrict__ o_t)
{
    long idx = (long)blockIdx.x * blockDim.x + threadIdx.x;
    if (idx >= CONV_TOTAL4) return;
    const float4* in; __half* out; long lidx;
    if (idx >= 458752L)       { in = t;  out = o_t; lidx = idx - 458752L; }
    else if (idx >= 393216L)  { in = wo; out = oo;  lidx = idx - 393216L; }
    else if (idx >= 196608L)  { in = wq; out = oq;  lidx = idx - 196608L; }
    else if (idx >= 131072L)  { in = wt; out = ot;  lidx = idx - 131072L; }
    else                      { in = wd; out = od;  lidx = idx; }
    float4 v = in[lidx];
    *(uint2*)(out + lidx * 4) =
        make_uint2(pk2h(__float2half_rn(v.x), __float2half_rn(v.y)),
                   pk2h(__float2half_rn(v.z), __float2half_rn(v.w)));
}

// ---------------------------------------------------------------------------
// GEMM: C[M,N] = A[M,K] @ W[N,K]^T + bias (+extra for MODE 1)
// Block 128x128, BK=64, 3-stage cp.async, 8 warps (2m x 4n), warp 64x32.
// CVT=1: A is fp32 in GMEM; LDG+convert+STS (registers), B stays cp.async.
// MODE 0: fp32 out, row stride N.
// MODE 1: fp16 out, row stride 512, adds extra[m>>3, col] (temb).
// MODE 2: fp16 out, row stride N.
// ---------------------------------------------------------------------------
#define STAGES      3
#define STAGE_BYTES 32768    // A 16KB + B 16KB

template <int MODE, int CVT>
__global__ __launch_bounds__(256, 2)
void gemm_mma(const void* __restrict__ Ain, const __half* __restrict__ B,
              const float* __restrict__ bias, const float* __restrict__ extra,
              void* __restrict__ Cout, int N, int K)
{
    extern __shared__ char sm[];
    const uint32_t smemBase = smem_u32(sm);
    const int tid    = threadIdx.x;
    const int lane   = tid & 31;
    const int wid    = tid >> 5;
    const int warp_m = wid >> 2;
    const int warp_n = wid & 3;
    const int mB     = blockIdx.y * 128;
    const int nB     = blockIdx.x * 128;

    const __half* Ah = (const __half*)Ain;
    const float*  Af = (const float*)Ain;

    // A: 1024 16B-chunks/stage, 4 per thread.  B: same.
    uint32_t dstA[4], dstB[4];
    const __half* gA16[4];
    const float*  gA32[4];
    const __half* gB[4];
#pragma unroll
    for (int j = 0; j < 4; j++) {
        int chunk = tid + 256 * j;
        int row = chunk >> 3, c = chunk & 7;
        uint32_t swz = (uint32_t)((c ^ (row & 7)) << 4);
        dstA[j] = row * 128 + swz;
        dstB[j] = 16384 + row * 128 + swz;
        if (CVT) gA32[j] = Af + (size_t)(mB + row) * K + c * 8;
        else     gA16[j] = Ah + (size_t)(mB + row) * K + c * 8;
        gB[j] = B + (size_t)(nB + row) * K + c * 8;
    }

    // ldmatrix bases (stage 0, k-chunk 0)
    const int la = lane & 15, ha = lane >> 4;
    uint32_t baseA[4];
#pragma unroll
    for (int mi = 0; mi < 4; mi++) {
        int row = warp_m * 64 + mi * 16 + la;
        baseA[mi] = smemBase + row * 128 + ((ha ^ (row & 7)) << 4);
    }
    const int lb = (lane & 7) + ((lane >> 4) << 3);
    const int hb = (lane >> 3) & 1;
    uint32_t baseB[2];
#pragma unroll
    for (int n2 = 0; n2 < 2; n2++) {
        int row = warp_n * 32 + n2 * 16 + lb;
        baseB[n2] = smemBase + 16384 + row * 128 + ((hb ^ (row & 7)) << 4);
    }

    float acc[4][4][4];
#pragma unroll
    for (int mi = 0; mi < 4; mi++)
#pragma unroll
        for (int ni = 0; ni < 4; ni++)
#pragma unroll
            for (int e = 0; e < 4; e++) acc[mi][ni][e] = 0.f;

    const int nIter = K >> 6;

    uint4 va[4];
    if (CVT) {
#pragma unroll
        for (int j = 0; j < 4; j++) va[j] = cvt8f(gA32[j]);    // iter 0
    }

    // prologue: 2 stages of B (and A when !CVT)
#pragma unroll
    for (int s = 0; s < STAGES - 1; s++) {
        const uint32_t sb = smemBase + s * STAGE_BYTES;
        if (!CVT) {
#pragma unroll
            for (int j = 0; j < 4; j++) CP_ASYNC(sb + dstA[j], gA16[j] + s * 64);
        }
#pragma unroll
        for (int j = 0; j < 4; j++) CP_ASYNC(sb + dstB[j], gB[j] + s * 64);
        CP_COMMIT();
    }

    int stage = 0;
    for (int it = 0; it < nIter; it++) {
        if (CVT) {
            const uint32_t sb = smemBase + stage * STAGE_BYTES;
#pragma unroll
            for (int j = 0; j < 4; j++) *(uint4*)(sm + (sb - smemBase) + dstA[j]) = va[j];
        }
        CP_WAIT(1);
        __syncthreads();

        if (it + STAGES - 1 < nIter) {
            const int pstage = (stage + STAGES - 1 >= STAGES) ? stage - 1 : stage + 2;
            const uint32_t sb = smemBase + pstage * STAGE_BYTES;
            const int off = (it + STAGES - 1) * 64;
            if (!CVT) {
#pragma unroll
                for (int j = 0; j < 4; j++) CP_ASYNC(sb + dstA[j], gA16[j] + off);
            }
#pragma unroll
            for (int j = 0; j < 4; j++) CP_ASYNC(sb + dstB[j], gB[j] + off);
        }
        if (CVT && it + 1 < nIter) {
            const int off = (it + 1) * 64;
#pragma unroll
            for (int j = 0; j < 4; j++) va[j] = cvt8f(gA32[j] + off);
        }
        CP_COMMIT();

        const uint32_t stOff = (uint32_t)stage * STAGE_BYTES;
#pragma unroll
        for (int kk = 0; kk < 4; kk++) {
            uint32_t a[4][4], b[2][4];
#pragma unroll
            for (int mi = 0; mi < 4; mi++)
                ldsm4(a[mi], (baseA[mi] + stOff) ^ (kk << 5));
#pragma unroll
            for (int n2 = 0; n2 < 2; n2++)
                ldsm4(b[n2], (baseB[n2] + stOff) ^ (kk << 5));
#pragma unroll
            for (int mi = 0; mi < 4; mi++)
#pragma unroll
                for (int ni = 0; ni < 4; ni++)
                    mma16816(acc[mi][ni], a[mi],
                             b[ni >> 1][(ni & 1) * 2], b[ni >> 1][(ni & 1) * 2 + 1]);
        }
        stage = (stage + 1 == STAGES) ? 0 : stage + 1;
    }

    // ---------------- epilogue (bias hoisted) ----------------
    const int mWarp = mB + warp_m * 64;
    const int nWarp = nB + warp_n * 32;
    float bv[4][2];
#pragma unroll
    for (int ni = 0; ni < 4; ni++) {
        const int col = nWarp + ni * 8 + (lane & 3) * 2;
        bv[ni][0] = __ldg(bias + col);
        bv[ni][1] = __ldg(bias + col + 1);
    }
#pragma unroll
    for (int mi = 0; mi < 4; mi++) {
#pragma unroll
        for (int ni = 0; ni < 4; ni++) {
            const int row0 = mWarp + mi * 16 + (lane >> 2);
            const int col  = nWarp + ni * 8 + (lane & 3) * 2;
            float v0 = acc[mi][ni][0] + bv[ni][0], v1 = acc[mi][ni][1] + bv[ni][1];
            float v2 = acc[mi][ni][2] + bv[ni][0], v3 = acc[mi][ni][3] + bv[ni][1];
            if (MODE == 1) {
                const float* e0 = extra + (size_t)(row0 >> 3) * OUT_CH + col;
                const float* e1 = extra + (size_t)((row0 + 8) >> 3) * OUT_CH + col;
                v0 += __ldg(e0); v1 += __ldg(e0 + 1);
                v2 += __ldg(e1); v3 += __ldg(e1 + 1);
            }
            if (MODE == 0) {
                float* c0 = (float*)Cout + (size_t)row0 * N + col;
                float* c1 = (float*)Cout + (size_t)(row0 + 8) * N + col;
                *(float2*)c0 = make_float2(v0, v1);
                *(float2*)c1 = make_float2(v2, v3);
            } else {
                const int stride = (MODE == 1) ? OUT_CH : N;
                __half* o0 = (__half*)Cout + (size_t)row0 * stride + col;
                __half* o1 = (__half*)Cout + (size_t)(row0 + 8) * stride + col;
                *(uint32_t*)o0 = pk2h(__float2half_rn(v0), __float2half_rn(v1));
                *(uint32_t*)o1 = pk2h(__float2half_rn(v2), __float2half_rn(v3));
            }
        }
    }
}

// ---------------------------------------------------------------------------
// Per-row attention: raw half2 smem, shuffle softmax, one barrier.
// Block = 256 threads = 4 rows x 64 (qh,kh) threads.
// ---------------------------------------------------------------------------
__global__ __launch_bounds__(256)
void attn_kernel(const __half* __restrict__ qkv, __half* __restrict__ out2)
{
    __shared__ __align__(16) __half s[4][1536];   // 12 KB

    const int tid = threadIdx.x;
    const size_t rowBase = (size_t)blockIdx.x * 4;

    const uint4* src = (const uint4*)(qkv + rowBase * 1536);
    uint4* dst = (uint4*)&s[0][0];
    dst[tid]       = src[tid];
    dst[256 + tid] = src[256 + tid];
    dst[512 + tid] = src[512 + tid];
    __syncthreads();

    const int r  = tid >> 6;
    const int j  = tid & 63;
    const int qh = j >> 3;
    const int kh = j & 7;

    const __half* q = &s[r][0];
    const __half* k = &s[r][512];
    const __half* v = &s[r][1024];

    float sc = 0.f;
#pragma unroll
    for (int c = 0; c < 8; c++) {
        const int cc = (kh + c) & 7;
        uint4 qu = *(const uint4*)(q + qh * 64 + cc * 8);
        uint4 ku = *(const uint4*)(k + kh * 64 + cc * 8);
        const __half2* qp = (const __half2*)&qu;
        const __half2* kp = (const __half2*)&ku;
#pragma unroll
        for (int e = 0; e < 4; e++) {
            float2 a = __half22float2(qp[e]);
            float2 b = __half22float2(kp[e]);
            sc += a.x * b.x + a.y * b.y;
        }
    }
    sc *= 0.125f;

    float mx = sc;
#pragma unroll
    for (int d = 1; d < 8; d <<= 1)
        mx = fmaxf(mx, __shfl_xor_sync(0xffffffffu, mx, d, 8));
    float e = __expf(sc - mx);
    float sum = e;
#pragma unroll
    for (int d = 1; d < 8; d <<= 1)
        sum += __shfl_xor_sync(0xffffffffu, sum, d, 8);
    const float wOwn = e / sum;

    const int lane = tid & 31;
    const int gBase = lane & 24;
    float o[8];
#pragma unroll
    for (int i = 0; i < 8; i++) o[i] = 0.f;
#pragma unroll
    for (int kk = 0; kk < 8; kk++) {
        const int kh2 = (kk + kh) & 7;
        const float wv = __shfl_sync(0xffffffffu, wOwn, gBase + kh2);
        uint4 vu = *(const uint4*)(v + kh2 * 64 + kh * 8);
        const __half2* vp = (const __half2*)&vu;
#pragma unroll
        for (int ee = 0; ee < 4; ee++) {
            float2 b = __half22float2(vp[ee]);
            o[2 * ee]     += wv * b.x;
            o[2 * ee + 1] += wv * b.y;
        }
    }

    uint4 hv = make_uint4(
        pk2h(__float2half_rn(o[0]), __float2half_rn(o[1])),
        pk2h(__float2half_rn(o[2]), __float2half_rn(o[3])),
        pk2h(__float2half_rn(o[4]), __float2half_rn(o[5])),
        pk2h(__float2half_rn(o[6]), __float2half_rn(o[7])));
    __half* base = out2 + (rowBase + r) * 512 + qh * 64 + kh * 8;
    *(uint4*)base = hv;
}

// ---------------------------------------------------------------------------
extern "C" void kernel_launch(void* const* d_in, const int* in_sizes, int n_in,
                              void* d_out, int out_size)
{
    const float* x      = (const float*)d_in[0];
    const float* t      = (const float*)d_in[1];
    const float* W_down = (const float*)d_in[2];
    const float* b_down = (const float*)d_in[3];
    const float* W_t    = (const float*)d_in[4];
    const float* b_t    = (const float*)d_in[5];
    const float* W_qkv  = (const float*)d_in[6];
    const float* b_qkv  = (const float*)d_in[7];
    const float* W_out  = (const float*)d_in[8];
    const float* b_out  = (const float*)d_in[9];
    float* out = (float*)d_out;

    void* p;
    __half *t16, *wd2, *wt2, *wq2, *wo2, *h2, *qkv, *at2;
    float *temb;
    cudaGetSymbolAddress(&p, g_t16);  t16 = (__half*)p;
    cudaGetSymbolAddress(&p, g_wd2);  wd2 = (__half*)p;
    cudaGetSymbolAddress(&p, g_wt2);  wt2 = (__half*)p;
    cudaGetSymbolAddress(&p, g_wq2);  wq2 = (__half*)p;
    cudaGetSymbolAddress(&p, g_wo2);  wo2 = (__half*)p;
    cudaGetSymbolAddress(&p, g_temb); temb = (float*)p;
    cudaGetSymbolAddress(&p, g_h2);   h2  = (__half*)p;
    cudaGetSymbolAddress(&p, g_qkv);  qkv = (__half*)p;
    cudaGetSymbolAddress(&p, g_at2);  at2 = (__half*)p;

    const int dynSmem = STAGES * STAGE_BYTES;   // 96 KB
    cudaFuncSetAttribute((const void*)gemm_mma<0, 0>, cudaFuncAttributeMaxDynamicSharedMemorySize, dynSmem);
    cudaFuncSetAttribute((const void*)gemm_mma<1, 1>, cudaFuncAttributeMaxDynamicSharedMemorySize, dynSmem);
    cudaFuncSetAttribute((const void*)gemm_mma<2, 0>, cudaFuncAttributeMaxDynamicSharedMemorySize, dynSmem);

    // 0: weights + t conversions (x handled in GEMM2)
    conv_all<<<(int)((CONV_TOTAL4 + 255) / 256), 256>>>(
        (const float4*)W_down, (const float4*)W_t,
        (const float4*)W_qkv, (const float4*)W_out,
        (const float4*)t,
        wd2, wt2, wq2, wo2, t16);

    // 1: temb = t @ W_t^T + b_t                       [8192, 512] fp32
    gemm_mma<0, 0><<<dim3(4, 64), 256, dynSmem>>>(t16, wt2, b_t, nullptr, temb,
                                                  OUT_CH, T_DIM);
    // 2: x2 = x(fp32) @ W_down^T + b_down + temb -> fp16 [65536, 512]
    gemm_mma<1, 1><<<dim3(4, 512), 256, dynSmem>>>(x, wd2, b_down, temb, h2,
                                                   OUT_CH, IN_CH);
    // 3: qkv = x2 @ W_qkv^T + b_qkv -> fp16           [65536, 1536]  (ncu slot)
    gemm_mma<2, 0><<<dim3(12, 512), 256, dynSmem>>>(h2, wq2, b_qkv, nullptr, qkv,
                                                    3 * OUT_CH, OUT_CH);
    // 4: attention -> fp16                            [65536, 512]
    attn_kernel<<<ROWS / 4, 256>>>(qkv, at2);
    // 5: out = attn @ W_out^T + b_out                 [65536, 512] fp32
    gemm_mma<0, 0><<<dim3(4, 512), 256, dynSmem>>>(at2, wo2, b_out, nullptr, out,
                                                   OUT_CH, OUT_CH);
}

// round 15
// speedup vs baseline: 1.1123x; 1.0368x over previous
#include <cuda_runtime.h>
#include <cuda_fp16.h>
#include <cstdint>
#include <cstddef>

// ---------------------------------------------------------------------------
// TSABlock, plain-fp16 mma.sync HMMA (tcgen05 blocked: harness PTX targets
// compute_103 without the 'a' feature set).
// GEMMs: A fp16, W fp16, fp32 accumulate (calibrated rel_err ~5.2e-4).
// R15 = R11 (best, 719.6us) + per-warp kk rotation in the GEMM mainloop:
// warp w processes k-chunks starting at (w&3), de-phasing the block-wide
// LDSM-burst / MMA-burst alternation that capped tensor and L1 both at ~60%.
// (R13/R14 CVT fusion reverted: grid.x=4 A-reread made fp32-A cost 1GB DRAM.)
// Attention fully row-local (HEADS==CLIP==8 torch-.view quirk).
// ---------------------------------------------------------------------------

#define BSZ     8192
#define IN_CH   1024
#define OUT_CH  512
#define T_DIM   512
#define ROWS    65536

__device__ __half g_t16 [(size_t)BSZ  * T_DIM];
__device__ __half g_x16 [(size_t)ROWS * IN_CH];
__device__ __half g_wd2 [(size_t)OUT_CH * IN_CH];
__device__ __half g_wt2 [(size_t)OUT_CH * T_DIM];
__device__ __half g_wq2 [(size_t)3 * OUT_CH * OUT_CH];
__device__ __half g_wo2 [(size_t)OUT_CH * OUT_CH];
__device__ float  g_temb[(size_t)BSZ * OUT_CH];
__device__ __half g_h2  [(size_t)ROWS * OUT_CH];
__device__ __half g_qkv [(size_t)ROWS * 3 * OUT_CH];
__device__ __half g_at2 [(size_t)ROWS * OUT_CH];

// ---------------------------- helpers --------------------------------------
__device__ __forceinline__ uint32_t smem_u32(const void* p) {
    uint32_t a;
    asm("{ .reg .u64 t; cvta.to.shared.u64 t, %1; cvt.u32.u64 %0, t; }"
        : "=r"(a) : "l"(p));
    return a;
}
__device__ __forceinline__ void ldsm4(uint32_t* r, uint32_t addr) {
    asm volatile("ldmatrix.sync.aligned.m8n8.x4.shared.b16 {%0,%1,%2,%3}, [%4];"
                 : "=r"(r[0]), "=r"(r[1]), "=r"(r[2]), "=r"(r[3]) : "r"(addr));
}
__device__ __forceinline__ void mma16816(float* d, const uint32_t* a,
                                         uint32_t b0, uint32_t b1) {
    asm volatile("mma.sync.aligned.m16n8k16.row.col.f32.f16.f16.f32 "
                 "{%0,%1,%2,%3}, {%4,%5,%6,%7}, {%8,%9}, {%0,%1,%2,%3};"
                 : "+f"(d[0]), "+f"(d[1]), "+f"(d[2]), "+f"(d[3])
                 : "r"(a[0]), "r"(a[1]), "r"(a[2]), "r"(a[3]), "r"(b0), "r"(b1));
}
#define CP_ASYNC(dst, src) \
    asm volatile("cp.async.cg.shared.global [%0], [%1], 16;" :: "r"(dst), "l"(src))
#define CP_COMMIT() asm volatile("cp.async.commit_group;" ::: "memory")
#define CP_WAIT(n)  asm volatile("cp.async.wait_group %0;" :: "n"(n) : "memory")

__device__ __forceinline__ uint32_t pk2h(__half a, __half b) {
    return (uint32_t)__half_as_ushort(a) | ((uint32_t)__half_as_ushort(b) << 16);
}

// ---------------------------------------------------------------------------
// conv_all: single elementwise fp32->fp16 pass over all 6 tensors.
// float4 region offsets:
//   wd [0,131072) wt [131072,196608) wq [196608,393216) wo [393216,458752)
//   t [458752,1507328)  x [1507328,18284544)
// ---------------------------------------------------------------------------
#define CONV_TOTAL4 18284544L

__global__ void conv_all(const float4* __restrict__ wd, const float4* __restrict__ wt,
                         const float4* __restrict__ wq, const float4* __restrict__ wo,
                         const float4* __restrict__ t,  const float4* __restrict__ x,
                         __half* __restrict__ od, __half* __restrict__ ot,
                         __half* __restrict__ oq, __half* __restrict__ oo,
                         __half* __restrict__ o_t, __half* __restrict__ o_x)
{
    long idx = (long)blockIdx.x * blockDim.x + threadIdx.x;
    if (idx >= CONV_TOTAL4) return;
    const float4* in; __half* out; long lidx;
    if (idx >= 1507328L)      { in = x;  out = o_x; lidx = idx - 1507328L; }
    else if (idx >= 458752L)  { in = t;  out = o_t; lidx = idx - 458752L; }
    else if (idx >= 393216L)  { in = wo; out = oo;  lidx = idx - 393216L; }
    else if (idx >= 196608L)  { in = wq; out = oq;  lidx = idx - 196608L; }
    else if (idx >= 131072L)  { in = wt; out = ot;  lidx = idx - 131072L; }
    else                      { in = wd; out = od;  lidx = idx; }
    float4 v = in[lidx];
    *(uint2*)(out + lidx * 4) =
        make_uint2(pk2h(__float2half_rn(v.x), __float2half_rn(v.y)),
                   pk2h(__float2half_rn(v.z), __float2half_rn(v.w)));
}

// ---------------------------------------------------------------------------
// GEMM: C[M,N] = A[M,K] @ W[N,K]^T + bias (+extra for MODE 1)
// Block 128x128, BK=64, 3-stage cp.async, 8 warps (2m x 4n), warp 64x32.
// Per-warp kk rotation: warp w starts its k-chunk walk at (w&3).
// MODE 0: fp32 out, row stride N.
// MODE 1: fp16 out, row stride 512, adds extra[m>>3, col] (temb).
// MODE 2: fp16 out, row stride N.
// ---------------------------------------------------------------------------
#define STAGES      3
#define STAGE_BYTES 32768    // A 16KB + B 16KB

template <int MODE>
__global__ __launch_bounds__(256, 2)
void gemm_mma(const __half* __restrict__ A, const __half* __restrict__ B,
              const float* __restrict__ bias, const float* __restrict__ extra,
              void* __restrict__ Cout, int N, int K)
{
    extern __shared__ char sm[];
    const uint32_t smemBase = smem_u32(sm);
    const int tid    = threadIdx.x;
    const int lane   = tid & 31;
    const int wid    = tid >> 5;
    const int warp_m = wid >> 2;
    const int warp_n = wid & 3;
    const int kkRot  = wid & 3;          // per-warp k-chunk phase
    const int mB     = blockIdx.y * 128;
    const int nB     = blockIdx.x * 128;

    // cp.async: 2048 16B chunks/stage (A 1024 + B 1024), 8 per thread
    uint32_t dstOff[8];
    const __half* gsrc[8];
#pragma unroll
    for (int j = 0; j < 8; j++) {
        int chunk = tid + 256 * j;
        int isB   = chunk >> 10;
        int cc    = chunk & 1023;
        int row   = cc >> 3, c = cc & 7;
        dstOff[j] = isB * 16384 + row * 128 + ((c ^ (row & 7)) << 4);
        gsrc[j] = (isB ? B + (size_t)(nB + row) * K
                       : A + (size_t)(mB + row) * K) + c * 8;
    }

    // ldmatrix bases (stage 0, k-chunk 0)
    const int la = lane & 15, ha = lane >> 4;
    uint32_t baseA[4];
#pragma unroll
    for (int mi = 0; mi < 4; mi++) {
        int row = warp_m * 64 + mi * 16 + la;
        baseA[mi] = smemBase + row * 128 + ((ha ^ (row & 7)) << 4);
    }
    const int lb = (lane & 7) + ((lane >> 4) << 3);
    const int hb = (lane >> 3) & 1;
    uint32_t baseB[2];
#pragma unroll
    for (int n2 = 0; n2 < 2; n2++) {
        int row = warp_n * 32 + n2 * 16 + lb;
        baseB[n2] = smemBase + 16384 + row * 128 + ((hb ^ (row & 7)) << 4);
    }

    float acc[4][4][4];
#pragma unroll
    for (int mi = 0; mi < 4; mi++)
#pragma unroll
        for (int ni = 0; ni < 4; ni++)
#pragma unroll
            for (int e = 0; e < 4; e++) acc[mi][ni][e] = 0.f;

    const int nIter = K >> 6;

    // prologue: 2 stages
#pragma unroll
    for (int s = 0; s < STAGES - 1; s++) {
#pragma unroll
        for (int j = 0; j < 8; j++)
            CP_ASYNC(smemBase + s * STAGE_BYTES + dstOff[j], gsrc[j] + s * 64);
        CP_COMMIT();
    }

    int stage = 0;
    for (int it = 0; it < nIter; it++) {
        CP_WAIT(1);
        __syncthreads();

        if (it + STAGES - 1 < nIter) {
            const int pstage = (stage + STAGES - 1 >= STAGES) ? stage - 1 : stage + 2;
            const uint32_t sb = smemBase + pstage * STAGE_BYTES;
            const int off = (it + STAGES - 1) * 64;
#pragma unroll
            for (int j = 0; j < 8; j++)
                CP_ASYNC(sb + dstOff[j], gsrc[j] + off);
        }
        CP_COMMIT();

        const uint32_t stOff = (uint32_t)stage * STAGE_BYTES;
#pragma unroll
        for (int kk = 0; kk < 4; kk++) {
            const int kkr = (kk + kkRot) & 3;     // de-phased k-chunk order
            uint32_t a[4][4], b[2][4];
#pragma unroll
            for (int mi = 0; mi < 4; mi++)
                ldsm4(a[mi], (baseA[mi] + stOff) ^ (kkr << 5));
#pragma unroll
            for (int n2 = 0; n2 < 2; n2++)
                ldsm4(b[n2], (baseB[n2] + stOff) ^ (kkr << 5));
#pragma unroll
            for (int mi = 0; mi < 4; mi++)
#pragma unroll
                for (int ni = 0; ni < 4; ni++)
                    mma16816(acc[mi][ni], a[mi],
                             b[ni >> 1][(ni & 1) * 2], b[ni >> 1][(ni & 1) * 2 + 1]);
        }
        stage = (stage + 1 == STAGES) ? 0 : stage + 1;
    }

    // ---------------- epilogue (bias hoisted) ----------------
    const int mWarp = mB + warp_m * 64;
    const int nWarp = nB + warp_n * 32;
    float bv[4][2];
#pragma unroll
    for (int ni = 0; ni < 4; ni++) {
        const int col = nWarp + ni * 8 + (lane & 3) * 2;
        bv[ni][0] = __ldg(bias + col);
        bv[ni][1] = __ldg(bias + col + 1);
    }
#pragma unroll
    for (int mi = 0; mi < 4; mi++) {
#pragma unroll
        for (int ni = 0; ni < 4; ni++) {
            const int row0 = mWarp + mi * 16 + (lane >> 2);
            const int col  = nWarp + ni * 8 + (lane & 3) * 2;
            float v0 = acc[mi][ni][0] + bv[ni][0], v1 = acc[mi][ni][1] + bv[ni][1];
            float v2 = acc[mi][ni][2] + bv[ni][0], v3 = acc[mi][ni][3] + bv[ni][1];
            if (MODE == 1) {
                const float* e0 = extra + (size_t)(row0 >> 3) * OUT_CH + col;
                const float* e1 = extra + (size_t)((row0 + 8) >> 3) * OUT_CH + col;
                v0 += __ldg(e0); v1 += __ldg(e0 + 1);
                v2 += __ldg(e1); v3 += __ldg(e1 + 1);
            }
            if (MODE == 0) {
                float* c0 = (float*)Cout + (size_t)row0 * N + col;
                float* c1 = (float*)Cout + (size_t)(row0 + 8) * N + col;
                *(float2*)c0 = make_float2(v0, v1);
                *(float2*)c1 = make_float2(v2, v3);
            } else {
                const int stride = (MODE == 1) ? OUT_CH : N;
                __half* o0 = (__half*)Cout + (size_t)row0 * stride + col;
                __half* o1 = (__half*)Cout + (size_t)(row0 + 8) * stride + col;
                *(uint32_t*)o0 = pk2h(__float2half_rn(v0), __float2half_rn(v1));
                *(uint32_t*)o1 = pk2h(__float2half_rn(v2), __float2half_rn(v3));
            }
        }
    }
}

// ---------------------------------------------------------------------------
// Per-row attention: raw half2 smem, shuffle softmax, one barrier.
// Block = 256 threads = 4 rows x 64 (qh,kh) threads.
// ---------------------------------------------------------------------------
__global__ __launch_bounds__(256)
void attn_kernel(const __half* __restrict__ qkv, __half* __restrict__ out2)
{
    __shared__ __align__(16) __half s[4][1536];   // 12 KB

    const int tid = threadIdx.x;
    const size_t rowBase = (size_t)blockIdx.x * 4;

    const uint4* src = (const uint4*)(qkv + rowBase * 1536);
    uint4* dst = (uint4*)&s[0][0];
    dst[tid]       = src[tid];
    dst[256 + tid] = src[256 + tid];
    dst[512 + tid] = src[512 + tid];
    __syncthreads();

    const int r  = tid >> 6;
    const int j  = tid & 63;
    const int qh = j >> 3;
    const int kh = j & 7;

    const __half* q = &s[r][0];
    const __half* k = &s[r][512];
    const __half* v = &s[r][1024];

    float sc = 0.f;
#pragma unroll
    for (int c = 0; c < 8; c++) {
        const int cc = (kh + c) & 7;
        uint4 qu = *(const uint4*)(q + qh * 64 + cc * 8);
        uint4 ku = *(const uint4*)(k + kh * 64 + cc * 8);
        const __half2* qp = (const __half2*)&qu;
        const __half2* kp = (const __half2*)&ku;
#pragma unroll
        for (int e = 0; e < 4; e++) {
            float2 a = __half22float2(qp[e]);
            float2 b = __half22float2(kp[e]);
            sc += a.x * b.x + a.y * b.y;
        }
    }
    sc *= 0.125f;

    float mx = sc;
#pragma unroll
    for (int d = 1; d < 8; d <<= 1)
        mx = fmaxf(mx, __shfl_xor_sync(0xffffffffu, mx, d, 8));
    float e = __expf(sc - mx);
    float sum = e;
#pragma unroll
    for (int d = 1; d < 8; d <<= 1)
        sum += __shfl_xor_sync(0xffffffffu, sum, d, 8);
    const float wOwn = e / sum;

    const int lane = tid & 31;
    const int gBase = lane & 24;
    float o[8];
#pragma unroll
    for (int i = 0; i < 8; i++) o[i] = 0.f;
#pragma unroll
    for (int kk = 0; kk < 8; kk++) {
        const int kh2 = (kk + kh) & 7;
        const float wv = __shfl_sync(0xffffffffu, wOwn, gBase + kh2);
        uint4 vu = *(const uint4*)(v + kh2 * 64 + kh * 8);
        const __half2* vp = (const __half2*)&vu;
#pragma unroll
        for (int ee = 0; ee < 4; ee++) {
            float2 b = __half22float2(vp[ee]);
            o[2 * ee]     += wv * b.x;
            o[2 * ee + 1] += wv * b.y;
        }
    }

    uint4 hv = make_uint4(
        pk2h(__float2half_rn(o[0]), __float2half_rn(o[1])),
        pk2h(__float2half_rn(o[2]), __float2half_rn(o[3])),
        pk2h(__float2half_rn(o[4]), __float2half_rn(o[5])),
        pk2h(__float2half_rn(o[6]), __float2half_rn(o[7])));
    __half* base = out2 + (rowBase + r) * 512 + qh * 64 + kh * 8;
    *(uint4*)base = hv;
}

// ---------------------------------------------------------------------------
extern "C" void kernel_launch(void* const* d_in, const int* in_sizes, int n_in,
                              void* d_out, int out_size)
{
    const float* x      = (const float*)d_in[0];
    const float* t      = (const float*)d_in[1];
    const float* W_down = (const float*)d_in[2];
    const float* b_down = (const float*)d_in[3];
    const float* W_t    = (const float*)d_in[4];
    const float* b_t    = (const float*)d_in[5];
    const float* W_qkv  = (const float*)d_in[6];
    const float* b_qkv  = (const float*)d_in[7];
    const float* W_out  = (const float*)d_in[8];
    const float* b_out  = (const float*)d_in[9];
    float* out = (float*)d_out;

    void* p;
    __half *t16, *x16, *wd2, *wt2, *wq2, *wo2, *h2, *qkv, *at2;
    float *temb;
    cudaGetSymbolAddress(&p, g_t16);  t16 = (__half*)p;
    cudaGetSymbolAddress(&p, g_x16);  x16 = (__half*)p;
    cudaGetSymbolAddress(&p, g_wd2);  wd2 = (__half*)p;
    cudaGetSymbolAddress(&p, g_wt2);  wt2 = (__half*)p;
    cudaGetSymbolAddress(&p, g_wq2);  wq2 = (__half*)p;
    cudaGetSymbolAddress(&p, g_wo2);  wo2 = (__half*)p;
    cudaGetSymbolAddress(&p, g_temb); temb = (float*)p;
    cudaGetSymbolAddress(&p, g_h2);   h2  = (__half*)p;
    cudaGetSymbolAddress(&p, g_qkv);  qkv = (__half*)p;
    cudaGetSymbolAddress(&p, g_at2);  at2 = (__half*)p;

    const int dynSmem = STAGES * STAGE_BYTES;   // 96 KB
    cudaFuncSetAttribute(gemm_mma<0>, cudaFuncAttributeMaxDynamicSharedMemorySize, dynSmem);
    cudaFuncSetAttribute(gemm_mma<1>, cudaFuncAttributeMaxDynamicSharedMemorySize, dynSmem);
    cudaFuncSetAttribute(gemm_mma<2>, cudaFuncAttributeMaxDynamicSharedMemorySize, dynSmem);

    // 0: all conversions in one wave
    conv_all<<<(int)((CONV_TOTAL4 + 255) / 256), 256>>>(
        (const float4*)W_down, (const float4*)W_t,
        (const float4*)W_qkv, (const float4*)W_out,
        (const float4*)t, (const float4*)x,
        wd2, wt2, wq2, wo2, t16, x16);

    // 1: temb = t @ W_t^T + b_t                       [8192, 512] fp32
    gemm_mma<0><<<dim3(4, 64), 256, dynSmem>>>(t16, wt2, b_t, nullptr, temb,
                                               OUT_CH, T_DIM);
    // 2: x2 = x @ W_down^T + b_down + temb -> fp16    [65536, 512]
    gemm_mma<1><<<dim3(4, 512), 256, dynSmem>>>(x16, wd2, b_down, temb, h2,
                                                OUT_CH, IN_CH);
    // 3: qkv = x2 @ W_qkv^T + b_qkv -> fp16           [65536, 1536]  (ncu slot)
    gemm_mma<2><<<dim3(12, 512), 256, dynSmem>>>(h2, wq2, b_qkv, nullptr, qkv,
                                                 3 * OUT_CH, OUT_CH);
    // 4: attention -> fp16                            [65536, 512]
    attn_kernel<<<ROWS / 4, 256>>>(qkv, at2);
    // 5: out = attn @ W_out^T + b_out                 [65536, 512] fp32
    gemm_mma<0><<<dim3(4, 512), 256, dynSmem>>>(at2, wo2, b_out, nullptr, out,
                                                OUT_CH, OUT_CH);
}